// round 1
// baseline (speedup 1.0000x reference)
#include <cuda_runtime.h>
#include <math.h>

#define NPTS 8192
#define BB   4
#define DD   128
#define KK   8
#define NB   (NPTS*BB)        // 32768
#define GST  132              // padded shared stride for GEMM tiles (16B aligned, bank-spread)

// ---------------- scratch (device globals: allocation-free) ----------------
__device__ float g_qf[BB*NPTS*DD];   // [B,N,D]
__device__ float g_kf[BB*NPTS*DD];
__device__ float g_vf[BB*NPTS*DD];
__device__ float g_res[BB*NPTS*DD];
__device__ int   g_idx[BB*NPTS*KK];

// ============================================================================
// GEMM: [32768,128] @ [128,128] (+bias, optional residual)
// mode 0/1/2: A=query [N,B,D] rows, out -> g_qf/g_kf/g_vf in [B,N,D]
// mode 3:     A=g_res permuted rows (b*N+n), out -> d_out [N,B,D] + query residual
// ============================================================================
__global__ __launch_bounds__(256, 1) void gemm_k(
    const float* __restrict__ Aext, const float* __restrict__ W,
    const float* __restrict__ bias, const float* __restrict__ resid,
    float* __restrict__ outext, int mode)
{
    extern __shared__ float smbuf[];
    float* Ats = smbuf;               // [128][GST], transposed: Ats[j*GST+m]
    float* Ws  = smbuf + 128*GST;     // [128][GST]: Ws[j*GST+d]

    const float* A = (mode == 3) ? (const float*)g_res : Aext;
    float* outp = (mode == 0) ? (float*)g_qf :
                  (mode == 1) ? (float*)g_kf :
                  (mode == 2) ? (float*)g_vf : outext;

    const int tid = threadIdx.x;
    const int m0  = blockIdx.x * 128;

    // load W tile (full 128x128)
    #pragma unroll 8
    for (int i = tid; i < DD*DD; i += 256) {
        int j = i >> 7, d = i & 127;
        Ws[j*GST + d] = W[i];
    }
    // load A tile transposed
    #pragma unroll 8
    for (int i = tid; i < 128*DD; i += 256) {
        int m = i >> 7, j = i & 127;
        int gm = m0 + m;
        int arow = (mode == 3) ? ((gm & 3) * NPTS + (gm >> 2)) : gm;
        Ats[j*GST + m] = A[(size_t)arow*DD + j];
    }
    __syncthreads();

    const int tx = tid & 15, ty = tid >> 4;
    const int r0 = ty * 8, c0 = tx * 8;

    float acc[8][8];
    #pragma unroll
    for (int r = 0; r < 8; r++)
        #pragma unroll
        for (int c = 0; c < 8; c++) acc[r][c] = 0.f;

    #pragma unroll 2
    for (int j = 0; j < 128; ++j) {
        const float4 a0 = *(const float4*)(Ats + j*GST + r0);
        const float4 a1 = *(const float4*)(Ats + j*GST + r0 + 4);
        const float4 w0 = *(const float4*)(Ws  + j*GST + c0);
        const float4 w1 = *(const float4*)(Ws  + j*GST + c0 + 4);
        float av[8] = {a0.x,a0.y,a0.z,a0.w,a1.x,a1.y,a1.z,a1.w};
        float wv[8] = {w0.x,w0.y,w0.z,w0.w,w1.x,w1.y,w1.z,w1.w};
        #pragma unroll
        for (int r = 0; r < 8; r++)
            #pragma unroll
            for (int c = 0; c < 8; c++)
                acc[r][c] = fmaf(av[r], wv[c], acc[r][c]);
    }

    float bv[8];
    #pragma unroll
    for (int c = 0; c < 8; c++) bv[c] = bias[c0 + c];

    #pragma unroll
    for (int r = 0; r < 8; r++) {
        int gm = m0 + r0 + r;
        float* orow;
        const float* rrow = 0;
        if (mode < 3) {
            orow = outp + (size_t)((gm & 3) * NPTS + (gm >> 2)) * DD;
        } else {
            orow = outp + (size_t)gm * DD;
            rrow = resid + (size_t)gm * DD;
        }
        #pragma unroll
        for (int c = 0; c < 8; c++) {
            float v = acc[r][c] + bv[c];
            if (mode == 3) v += rrow[c0 + c];
            orow[c0 + c] = v;
        }
    }
}

// ============================================================================
// Brute-force KNN (K=8, self included), matching the reference's
// d2 = |a|^2 + |b|^2 - 2 a.b formulation in fp32.
// ============================================================================
__global__ __launch_bounds__(256, 1) void knn_k(const float* __restrict__ pos)
{
    __shared__ float4 cand[1024];
    const int b = blockIdx.y;
    const int n = blockIdx.x * 256 + threadIdx.x;
    const float* pb = pos + (size_t)b * NPTS * 3;

    const float qx = pb[n*3], qy = pb[n*3+1], qz = pb[n*3+2];
    const float qsq = fmaf(qz, qz, fmaf(qy, qy, qx*qx));

    float bd[8]; int bi[8];
    #pragma unroll
    for (int k = 0; k < 8; k++) { bd[k] = 1e30f; bi[k] = 0; }

    for (int t = 0; t < NPTS; t += 1024) {
        __syncthreads();
        for (int i = threadIdx.x; i < 1024; i += 256) {
            float x = pb[(t+i)*3], y = pb[(t+i)*3+1], z = pb[(t+i)*3+2];
            cand[i] = make_float4(x, y, z, fmaf(z, z, fmaf(y, y, x*x)));
        }
        __syncthreads();
        #pragma unroll 4
        for (int m = 0; m < 1024; ++m) {
            float4 c = cand[m];
            float dot = fmaf(qz, c.z, fmaf(qy, c.y, qx * c.x));
            float d2  = fmaf(-2.f, dot, qsq + c.w);
            if (d2 < bd[7]) {
                bd[7] = d2; bi[7] = t + m;
                #pragma unroll
                for (int r = 7; r > 0; --r) {
                    if (bd[r] < bd[r-1]) {
                        float td = bd[r]; bd[r] = bd[r-1]; bd[r-1] = td;
                        int   ti = bi[r]; bi[r] = bi[r-1]; bi[r-1] = ti;
                    }
                }
            }
        }
    }
    int* op = g_idx + ((size_t)b * NPTS + n) * KK;
    #pragma unroll
    for (int k = 0; k < 8; k++) op[k] = bi[k];
}

// ============================================================================
// Fused per-point kernel: pe = Lin2(gelu(Lin1(rel))), a = (q-k+pe)@Wg+bg,
// softmax over feature dim, res = sum_k sm*(v+pe).
// 512 threads = 4 sub-blocks of 128; each sub-block owns one point.
// Weights resident in shared; persistent grid.
// Shared layout (floats):
//   Wp2s[16384] Wgs[16384] Wp1s[384] bp1[128] bp2[128] bg[128]
//   h_t[4*1024] u_t[4*1024] rel[4*32] redA[4*32] redB[4*32] idx[4*8]
// ============================================================================
#define FSM_WP2 0
#define FSM_WG  16384
#define FSM_WP1 32768
#define FSM_BP1 33152
#define FSM_BP2 33280
#define FSM_BG  33408
#define FSM_H   33536
#define FSM_U   37632
#define FSM_REL 41728
#define FSM_RA  41856
#define FSM_RB  41984
#define FSM_IDX 42112
#define FUSED_SMEM_FLOATS 42144
#define FUSED_SMEM_BYTES  (FUSED_SMEM_FLOATS*4)

__global__ __launch_bounds__(512, 1) void fused_k(
    const float* __restrict__ pos,
    const float* __restrict__ Wp1, const float* __restrict__ bp1,
    const float* __restrict__ Wp2, const float* __restrict__ bp2,
    const float* __restrict__ Wg,  const float* __restrict__ bg,
    int nTasks)
{
    extern __shared__ float sm[];
    float* Wp2s = sm + FSM_WP2;
    float* Wgs  = sm + FSM_WG;
    float* Wp1s = sm + FSM_WP1;
    float* bp1s = sm + FSM_BP1;
    float* bp2s = sm + FSM_BP2;
    float* bgs  = sm + FSM_BG;

    const int tid  = threadIdx.x;
    const int sub  = tid >> 7;       // 0..3 : which point of the quad
    const int d    = tid & 127;      // feature index
    const int lane = tid & 31;
    const int wsub = (tid >> 5) & 3; // warp within sub-block

    for (int i = tid; i < DD*DD; i += 512) { Wp2s[i] = Wp2[i]; Wgs[i] = Wg[i]; }
    for (int i = tid; i < 3*DD; i += 512) Wp1s[i] = Wp1[i];
    if (tid < DD) { bp1s[tid] = bp1[tid]; bp2s[tid] = bp2[tid]; bgs[tid] = bg[tid]; }
    __syncthreads();

    float* my_h   = sm + FSM_H   + sub * 1024;   // [j][k], stride 8
    float* my_u   = sm + FSM_U   + sub * 1024;   // [j][k], stride 8
    float* my_rel = sm + FSM_REL + sub * 32;     // [k][4]
    float* my_rA  = sm + FSM_RA  + sub * 32;     // warp partials (max)
    float* my_rB  = sm + FSM_RB  + sub * 32;     // warp partials (sum)
    int*   my_idx = (int*)(sm + FSM_IDX) + sub * 8;

    const float w0 = Wp1s[d], w1 = Wp1s[128 + d], w2 = Wp1s[256 + d];
    const float bb1 = bp1s[d], bb2 = bp2s[d], bbg = bgs[d];
    const float scale = 0.08838834764831845f;    // 1/sqrt(128)

    for (int task = blockIdx.x; task < nTasks; task += gridDim.x) {
        const int g = task * 4 + sub;
        const int b = g >> 13;
        const int n = g & (NPTS - 1);
        const float* kbase = g_kf + (size_t)b * NPTS * DD;
        const float* vbase = g_vf + (size_t)b * NPTS * DD;

        if (d < 8) {
            int id = g_idx[(size_t)g * KK + d];
            my_idx[d] = id;
            const float* pb = pos + (size_t)b * NPTS * 3;
            my_rel[d*4+0] = pb[n*3+0] - pb[id*3+0];
            my_rel[d*4+1] = pb[n*3+1] - pb[id*3+1];
            my_rel[d*4+2] = pb[n*3+2] - pb[id*3+2];
        }
        __syncthreads();

        // phase 1: h[j=d][k] = gelu(rel[k] . Wp1[:,d] + bp1[d])
        #pragma unroll
        for (int k = 0; k < 8; ++k) {
            float z = fmaf(my_rel[k*4+2], w2,
                      fmaf(my_rel[k*4+1], w1,
                      fmaf(my_rel[k*4+0], w0, bb1)));
            my_h[d*8 + k] = 0.5f * z * (1.f + erff(z * 0.70710678118654752f));
        }
        __syncthreads();

        // phase 2: pe[k] (feature d) = h[k] . Wp2[:,d] + bp2[d]  -- stays in regs
        float pe[8];
        #pragma unroll
        for (int k = 0; k < 8; ++k) pe[k] = bb2;
        {
            const float*  wp = Wp2s + d;
            const float4* hp = (const float4*)my_h;
            #pragma unroll 4
            for (int j = 0; j < 128; ++j) {
                float  w  = wp[j * 128];
                float4 ha = hp[2*j];
                float4 hb = hp[2*j + 1];
                pe[0] = fmaf(ha.x, w, pe[0]); pe[1] = fmaf(ha.y, w, pe[1]);
                pe[2] = fmaf(ha.z, w, pe[2]); pe[3] = fmaf(ha.w, w, pe[3]);
                pe[4] = fmaf(hb.x, w, pe[4]); pe[5] = fmaf(hb.y, w, pe[5]);
                pe[6] = fmaf(hb.z, w, pe[6]); pe[7] = fmaf(hb.w, w, pe[7]);
            }
        }
        // build u[j=d][k] = q[d] - k_knn[k][d] + pe[k]
        {
            float qv = g_qf[((size_t)b * NPTS + n) * DD + d];
            #pragma unroll
            for (int k = 0; k < 8; ++k) {
                float kv = kbase[(size_t)my_idx[k] * DD + d];
                my_u[d*8 + k] = qv - kv + pe[k];
            }
        }
        __syncthreads();

        // phase 3: a[k] (feature d) = u[k] . Wg[:,d] + bg[d]
        float a[8];
        #pragma unroll
        for (int k = 0; k < 8; ++k) a[k] = bbg;
        {
            const float*  wp = Wgs + d;
            const float4* up = (const float4*)my_u;
            #pragma unroll 4
            for (int j = 0; j < 128; ++j) {
                float  w  = wp[j * 128];
                float4 ua = up[2*j];
                float4 ub = up[2*j + 1];
                a[0] = fmaf(ua.x, w, a[0]); a[1] = fmaf(ua.y, w, a[1]);
                a[2] = fmaf(ua.z, w, a[2]); a[3] = fmaf(ua.w, w, a[3]);
                a[4] = fmaf(ub.x, w, a[4]); a[5] = fmaf(ub.y, w, a[5]);
                a[6] = fmaf(ub.z, w, a[6]); a[7] = fmaf(ub.w, w, a[7]);
            }
        }

        // softmax over feature dim (128 threads) for each k
        #pragma unroll
        for (int k = 0; k < 8; ++k) a[k] *= scale;

        float red[8];
        #pragma unroll
        for (int k = 0; k < 8; ++k) red[k] = a[k];
        #pragma unroll
        for (int off = 16; off > 0; off >>= 1)
            #pragma unroll
            for (int k = 0; k < 8; ++k)
                red[k] = fmaxf(red[k], __shfl_xor_sync(0xffffffffu, red[k], off));
        if (lane == 0) {
            #pragma unroll
            for (int k = 0; k < 8; ++k) my_rA[wsub*8 + k] = red[k];
        }
        __syncthreads();

        float e[8];
        #pragma unroll
        for (int k = 0; k < 8; ++k) {
            float bm = fmaxf(fmaxf(my_rA[k], my_rA[8+k]), fmaxf(my_rA[16+k], my_rA[24+k]));
            e[k] = __expf(a[k] - bm);
            red[k] = e[k];
        }
        #pragma unroll
        for (int off = 16; off > 0; off >>= 1)
            #pragma unroll
            for (int k = 0; k < 8; ++k)
                red[k] += __shfl_xor_sync(0xffffffffu, red[k], off);
        if (lane == 0) {
            #pragma unroll
            for (int k = 0; k < 8; ++k) my_rB[wsub*8 + k] = red[k];
        }
        __syncthreads();

        float rsum = 0.f;
        #pragma unroll
        for (int k = 0; k < 8; ++k) {
            float tot = (my_rB[k] + my_rB[8+k]) + (my_rB[16+k] + my_rB[24+k]);
            float smx = e[k] / tot;
            float v = vbase[(size_t)my_idx[k] * DD + d];
            rsum = fmaf(smx, v + pe[k], rsum);
        }
        g_res[((size_t)b * NPTS + n) * DD + d] = rsum;
        __syncthreads();
    }
}

// ============================================================================
// host launch
// ============================================================================
#define GEMM_SMEM (2*128*GST*4)

extern "C" void kernel_launch(void* const* d_in, const int* in_sizes, int n_in,
                              void* d_out, int out_size)
{
    const float* query = (const float*)d_in[0];
    const float* pos   = (const float*)d_in[1];
    const float* Wq  = (const float*)d_in[2];  const float* bq  = (const float*)d_in[3];
    const float* Wk  = (const float*)d_in[4];  const float* bk  = (const float*)d_in[5];
    const float* Wv  = (const float*)d_in[6];  const float* bv  = (const float*)d_in[7];
    const float* Wp1 = (const float*)d_in[8];  const float* bp1 = (const float*)d_in[9];
    const float* Wp2 = (const float*)d_in[10]; const float* bp2 = (const float*)d_in[11];
    const float* Wg  = (const float*)d_in[12]; const float* bg  = (const float*)d_in[13];
    const float* Wo  = (const float*)d_in[14]; const float* bo  = (const float*)d_in[15];
    float* out = (float*)d_out;

    cudaFuncSetAttribute(gemm_k,  cudaFuncAttributeMaxDynamicSharedMemorySize, GEMM_SMEM);
    cudaFuncSetAttribute(fused_k, cudaFuncAttributeMaxDynamicSharedMemorySize, FUSED_SMEM_BYTES);

    int dev = 0, sms = 148;
    cudaGetDevice(&dev);
    cudaDeviceGetAttribute(&sms, cudaDevAttrMultiProcessorCount, dev);

    // QKV projections -> g_qf/g_kf/g_vf in [B,N,D]
    gemm_k<<<NB/128, 256, GEMM_SMEM>>>(query, Wq, bq, (const float*)0, (float*)0, 0);
    gemm_k<<<NB/128, 256, GEMM_SMEM>>>(query, Wk, bk, (const float*)0, (float*)0, 1);
    gemm_k<<<NB/128, 256, GEMM_SMEM>>>(query, Wv, bv, (const float*)0, (float*)0, 2);

    // KNN indices
    knn_k<<<dim3(NPTS/256, BB), 256>>>(pos);

    // fused per-point attention
    fused_k<<<sms, 512, FUSED_SMEM_BYTES>>>(pos, Wp1, bp1, Wp2, bp2, Wg, bg, NB/4);

    // output projection + residual -> [N,B,D]
    gemm_k<<<NB/128, 256, GEMM_SMEM>>>(query, Wo, bo, query, out, 3);
}